// round 2
// baseline (speedup 1.0000x reference)
#include <cuda_runtime.h>
#include <cuda_bf16.h>
#include <math.h>

// ---------------- problem constants ----------------
#define BB    128          // batch
#define TLEN  500          // time steps
#define TP    512          // padded row stride (power of 2)
#define CH    128          // n_maps
#define NMELS 80
#define NLAB  35
#define NELEM 64000.0f     // BB * TLEN (per-channel BN count)

#define TOT (128*128*512)  // elements per feature tensor (c,b,t-padded) = 8.4M

// ---------------- scratch (device globals: no allocation allowed) ----------------
__device__ float g_Z[TOT];
__device__ float g_K[TOT];
__device__ float g_Y1[TOT];
__device__ float g_Y2[TOT];
__device__ float g_Y3[TOT];
__device__ float g_ZACC[TOT];

__device__ float g_W0t[3 * 80 * 128];
__device__ float g_W1t[9 * 128 * 128];
__device__ float g_W2t[9 * 128 * 128];
__device__ float g_W3t[1 * 128 * 128];

__device__ float g_sum1[128], g_ssq1[128], g_m1[128], g_r1[128];
__device__ float g_sum2[128], g_ssq2[128], g_m2[128], g_r2[128];
__device__ float g_sum3[128], g_ssq3[128], g_m3[128], g_r3[128];

// ---------------- helpers ----------------
__global__ void init_stats_kernel() {
    int c = threadIdx.x;
    if (c < 128) {
        g_sum1[c] = 0.f; g_ssq1[c] = 0.f;
        g_sum2[c] = 0.f; g_ssq2[c] = 0.f;
        g_sum3[c] = 0.f; g_ssq3[c] = 0.f;
    }
}

// dst[(k*CI + ci)*CO + co] = src[(co*CI + ci)*NK + k]
__global__ void transpose_w_kernel(const float* __restrict__ src, float* __restrict__ dst,
                                   int CO, int CI, int NK) {
    int idx = blockIdx.x * 256 + threadIdx.x;
    int tot = CO * CI * NK;
    if (idx < tot) {
        int co = idx / (CI * NK);
        int r  = idx % (CI * NK);
        int ci = r / NK;
        int k  = r % NK;
        dst[(k * CI + ci) * CO + co] = src[idx];
    }
}

// finalize per-channel mean/rstd from sums (biased var), then reset sums.
__global__ void finalize_stats_kernel(float* s1, float* q1, float* m1, float* r1,
                                      float* s2, float* q2, float* m2, float* r2) {
    int c = threadIdx.x;
    if (c >= 128) return;
    const float invN = 1.0f / NELEM;
    float m = s1[c] * invN;
    float v = q1[c] * invN - m * m;
    m1[c] = m; r1[c] = rsqrtf(v + 1e-5f);
    s1[c] = 0.f; q1[c] = 0.f;
    if (s2 != nullptr) {
        m = s2[c] * invN;
        v = q2[c] * invN - m * m;
        m2[c] = m; r2[c] = rsqrtf(v + 1e-5f);
        s2[c] = 0.f; q2[c] = 0.f;
    }
}

// Z = relu((Y - m)*r)   (elementwise over (c,b,t<500))
__global__ void bn_relu_kernel(const float* __restrict__ Y,
                               const float* __restrict__ m, const float* __restrict__ r,
                               float* __restrict__ Z) {
    int row = blockIdx.x;          // row = c*128 + b
    int c = row >> 7;
    float mm = m[c], rr = r[c];
    int base = row * TP;
    for (int t = threadIdx.x; t < TLEN; t += 128)
        Z[base + t] = fmaxf((Y[base + t] - mm) * rr, 0.f);
}

// k = relu(bn(Y2) + relu(bn(Y3)));  K = k;  RK4 accumulator updates.
// mode 0: ZACC = Z + w*k      (first eval of a step)
// mode 1: ZACC += w*k
// mode 2: Zout = ZACC + w*k   (last eval: produce next z)
__global__ void combine_kernel(const float* __restrict__ Y2, const float* __restrict__ Y3,
                               const float* __restrict__ m2, const float* __restrict__ r2,
                               const float* __restrict__ m3, const float* __restrict__ r3,
                               const float* __restrict__ Z, float* __restrict__ K,
                               float* __restrict__ ZA, float* __restrict__ Zout,
                               float wgt, int mode) {
    int row = blockIdx.x;
    int c = row >> 7;
    float mm2 = m2[c], rr2 = r2[c], mm3 = m3[c], rr3 = r3[c];
    int base = row * TP;
    for (int t = threadIdx.x; t < TLEN; t += 128) {
        int i = base + t;
        float y3n = fmaxf((Y3[i] - mm3) * rr3, 0.f);
        float k = fmaxf((Y2[i] - mm2) * rr2 + y3n, 0.f);
        K[i] = k;
        if (mode == 0)      ZA[i] = Z[i] + wgt * k;
        else if (mode == 1) ZA[i] = ZA[i] + wgt * k;
        else                Zout[i] = ZA[i] + wgt * k;
    }
}

// ---------------- tiled conv (implicit GEMM) ----------------
// out[co][b][t] = sum_{ci,k} wt[k][ci][co] * a[ci][b][t + k - R]
// where a = (in [+ alpha*in2]) then optional relu(bn(.)), zero outside t in [0,500).
// Tile: 128 co x 128 t per block; thread = 8co x 8t. grid = (4 t-tiles, 128 b).
template <int NTAPS, int CIN, bool RAW>
__global__ __launch_bounds__(256, 2) void conv_kernel(
    const float* __restrict__ in, const float* __restrict__ in2, float alpha,
    const float* __restrict__ wt,
    const float* __restrict__ bnm, const float* __restrict__ bnr,
    float* __restrict__ out, float* __restrict__ osum, float* __restrict__ ossq) {

    constexpr int R  = NTAPS / 2;
    constexpr int AW = 128 + NTAPS - 1;   // <= 136
    constexpr int CK = 8;

    __shared__ float As[CK][136];
    __shared__ float Ws[NTAPS][CK][128];

    const int t0  = blockIdx.x * 128;
    const int b   = blockIdx.y;
    const int tid = threadIdx.x;
    const int cid = tid & 15;     // co group
    const int tgi = tid >> 4;     // t group
    const int co0 = cid * 8;
    const int tl0 = tgi * 8;

    float acc[8][8];
#pragma unroll
    for (int i = 0; i < 8; i++)
#pragma unroll
        for (int j = 0; j < 8; j++) acc[i][j] = 0.f;

    const bool has2 = (in2 != nullptr);
    const bool hasbn = (bnm != nullptr);

#pragma unroll 1
    for (int cc = 0; cc < CIN / CK; ++cc) {
        __syncthreads();
        // stage A slice: CK channels x AW columns
        for (int idx = tid; idx < CK * AW; idx += 256) {
            int ci = idx / AW;
            int j  = idx % AW;
            int gc = t0 - R + j;
            float v = 0.f;
            if (gc >= 0 && gc < TLEN) {
                int cg = cc * CK + ci;
                int off;
                if (RAW) off = (b * CIN + cg) * TLEN + gc;      // x: [B][CIN][T]
                else     off = (cg * BB + b) * TP + gc;          // padded feature layout
                v = in[off];
                if (has2) v += alpha * in2[off];
                if (hasbn) v = fmaxf((v - bnm[cg]) * bnr[cg], 0.f);
            }
            As[ci][j] = v;
        }
        // stage W chunk: all taps, CK channels, 128 co (co contiguous)
        for (int idx = tid; idx < NTAPS * CK * 128; idx += 256) {
            int k  = idx / (CK * 128);
            int r  = idx % (CK * 128);
            int ci = r >> 7;
            int co = r & 127;
            Ws[k][ci][co] = wt[(k * CIN + cc * CK + ci) * 128 + co];
        }
        __syncthreads();

#pragma unroll 1
        for (int ci = 0; ci < CK; ++ci) {
            float aw[8 + NTAPS - 1];
#pragma unroll
            for (int q = 0; q < 8 + NTAPS - 1; ++q) aw[q] = As[ci][tl0 + q];
#pragma unroll
            for (int k = 0; k < NTAPS; ++k) {
                float w8[8];
#pragma unroll
                for (int i = 0; i < 8; i++) w8[i] = Ws[k][ci][co0 + i];
#pragma unroll
                for (int i = 0; i < 8; i++)
#pragma unroll
                    for (int j = 0; j < 8; j++)
                        acc[i][j] = fmaf(w8[i], aw[k + j], acc[i][j]);
            }
        }
    }

    // store + per-channel partial stats
    float s[8], q[8];
#pragma unroll
    for (int i = 0; i < 8; i++) { s[i] = 0.f; q[i] = 0.f; }

#pragma unroll
    for (int i = 0; i < 8; i++) {
        int co = co0 + i;
        int rowoff = (co * BB + b) * TP;
#pragma unroll
        for (int j = 0; j < 8; j++) {
            int tg = t0 + tl0 + j;
            if (tg < TLEN) {
                float v = acc[i][j];
                out[rowoff + tg] = v;
                s[i] += v;
                q[i] += v * v;
            }
        }
    }
    // lanes l and l^16 share the same co set (cid = tid & 15)
#pragma unroll
    for (int i = 0; i < 8; i++) {
        s[i] += __shfl_xor_sync(0xffffffffu, s[i], 16);
        q[i] += __shfl_xor_sync(0xffffffffu, q[i], 16);
    }
    if ((tid & 31) < 16) {
#pragma unroll
        for (int i = 0; i < 8; i++) {
            atomicAdd(&osum[co0 + i], s[i]);
            atomicAdd(&ossq[co0 + i], q[i]);
        }
    }
}

// ---------------- pool + head ----------------
__global__ void pool_head_kernel(const float* __restrict__ Z,
                                 const float* __restrict__ ow, const float* __restrict__ ob,
                                 float* __restrict__ out) {
    __shared__ float feat[128];
    int b = blockIdx.x;
    int c = threadIdx.x;
    const float* row = Z + (c * BB + b) * TP;
    float sum = 0.f;
    for (int t = 0; t < TLEN; t++) sum += row[t];
    feat[c] = sum * (1.0f / (float)TLEN);
    __syncthreads();
    if (c < NLAB) {
        float o = ob[c];
        for (int k = 0; k < 128; k++) o = fmaf(feat[k], ow[c * 128 + k], o);
        out[b * NLAB + c] = o;
    }
}

// ---------------- launch ----------------
extern "C" void kernel_launch(void* const* d_in, const int* in_sizes, int n_in,
                              void* d_out, int out_size) {
    const float* x   = (const float*)d_in[0];   // [128][80][500]
    const float* w0  = (const float*)d_in[1];   // [128][80][3][1]
    const float* w1  = (const float*)d_in[2];   // [128][128][9][1]
    const float* w2  = (const float*)d_in[3];   // [128][128][9][1]
    const float* w3  = (const float*)d_in[4];   // [128][128][1][1]
    const float* ow  = (const float*)d_in[5];   // [35][128]
    const float* ob  = (const float*)d_in[6];   // [35]
    float* out = (float*)d_out;

    float *pZ, *pK, *pY1, *pY2, *pY3, *pZA;
    float *pW0, *pW1, *pW2, *pW3;
    float *ps1, *pq1, *pm1, *pr1, *ps2, *pq2, *pm2, *pr2, *ps3, *pq3, *pm3, *pr3;
    cudaGetSymbolAddress((void**)&pZ, g_Z);
    cudaGetSymbolAddress((void**)&pK, g_K);
    cudaGetSymbolAddress((void**)&pY1, g_Y1);
    cudaGetSymbolAddress((void**)&pY2, g_Y2);
    cudaGetSymbolAddress((void**)&pY3, g_Y3);
    cudaGetSymbolAddress((void**)&pZA, g_ZACC);
    cudaGetSymbolAddress((void**)&pW0, g_W0t);
    cudaGetSymbolAddress((void**)&pW1, g_W1t);
    cudaGetSymbolAddress((void**)&pW2, g_W2t);
    cudaGetSymbolAddress((void**)&pW3, g_W3t);
    cudaGetSymbolAddress((void**)&ps1, g_sum1); cudaGetSymbolAddress((void**)&pq1, g_ssq1);
    cudaGetSymbolAddress((void**)&pm1, g_m1);   cudaGetSymbolAddress((void**)&pr1, g_r1);
    cudaGetSymbolAddress((void**)&ps2, g_sum2); cudaGetSymbolAddress((void**)&pq2, g_ssq2);
    cudaGetSymbolAddress((void**)&pm2, g_m2);   cudaGetSymbolAddress((void**)&pr2, g_r2);
    cudaGetSymbolAddress((void**)&ps3, g_sum3); cudaGetSymbolAddress((void**)&pq3, g_ssq3);
    cudaGetSymbolAddress((void**)&pm3, g_m3);   cudaGetSymbolAddress((void**)&pr3, g_r3);

    const float dt = 1.0f / 4.0f;           // INTEGRATION_TIME / NSTEPS
    dim3 cgrid(4, 128);                     // 4 t-tiles x 128 batches
    const int rows = 128 * 128;             // (c, b) rows

    init_stats_kernel<<<1, 128>>>();

    // transpose weights to [k][ci][co]
    transpose_w_kernel<<<(128 * 80 * 3 + 255) / 256, 256>>>(w0, pW0, 128, 80, 3);
    transpose_w_kernel<<<(128 * 128 * 9 + 255) / 256, 256>>>(w1, pW1, 128, 128, 9);
    transpose_w_kernel<<<(128 * 128 * 9 + 255) / 256, 256>>>(w2, pW2, 128, 128, 9);
    transpose_w_kernel<<<(128 * 128 * 1 + 255) / 256, 256>>>(w3, pW3, 128, 128, 1);

    // conv0 + BN + relu -> Z
    conv_kernel<3, 80, true><<<cgrid, 256>>>(x, nullptr, 0.f, pW0, nullptr, nullptr,
                                             pY1, ps1, pq1);
    finalize_stats_kernel<<<1, 128>>>(ps1, pq1, pm1, pr1, nullptr, nullptr, nullptr, nullptr);
    bn_relu_kernel<<<rows, 128>>>(pY1, pm1, pr1, pZ);

    // 4 RK4 steps x 4 odefunc evals
    for (int step = 0; step < 4; ++step) {
        for (int e = 0; e < 4; ++e) {
            float alpha = (e == 0) ? 0.f : (e == 3 ? dt : 0.5f * dt);
            const float* in2 = (e == 0) ? nullptr : (const float*)pK;

            // conv1(z + alpha*k)  -> Y1 (+stats1)
            conv_kernel<9, 128, false><<<cgrid, 256>>>(pZ, in2, alpha, pW1,
                                                       nullptr, nullptr, pY1, ps1, pq1);
            // conv3(z + alpha*k)  -> Y3 (+stats3)
            conv_kernel<1, 128, false><<<cgrid, 256>>>(pZ, in2, alpha, pW3,
                                                       nullptr, nullptr, pY3, ps3, pq3);
            finalize_stats_kernel<<<1, 128>>>(ps1, pq1, pm1, pr1, ps3, pq3, pm3, pr3);

            // conv2(relu(bn(Y1))) -> Y2 (+stats2)
            conv_kernel<9, 128, false><<<cgrid, 256>>>(pY1, nullptr, 0.f, pW2,
                                                       pm1, pr1, pY2, ps2, pq2);
            finalize_stats_kernel<<<1, 128>>>(ps2, pq2, pm2, pr2, nullptr, nullptr, nullptr, nullptr);

            // k = relu(bn(Y2) + relu(bn(Y3)));  RK4 accumulation
            float wgt = (dt / 6.0f) * ((e == 0 || e == 3) ? 1.0f : 2.0f);
            int mode = (e == 0) ? 0 : (e == 3 ? 2 : 1);
            combine_kernel<<<rows, 128>>>(pY2, pY3, pm2, pr2, pm3, pr3,
                                          pZ, pK, pZA, pZ, wgt, mode);
        }
    }

    // global average pool + linear head
    pool_head_kernel<<<128, 128>>>(pZ, ow, ob, out);
}

// round 3
// speedup vs baseline: 1.0027x; 1.0027x over previous
#include <cuda_runtime.h>
#include <cuda_bf16.h>
#include <math.h>

// ---------------- problem constants ----------------
#define BB    128          // batch
#define TLEN  500          // time steps
#define TP    512          // padded row stride (power of 2)
#define CH    128          // n_maps
#define NMELS 80
#define NLAB  35
#define NELEM 64000.0f     // BB * TLEN (per-channel BN count)

#define TOT (128*128*512)  // elements per feature tensor (c,b,t-padded) = 8.4M

// ---------------- scratch (device globals: no allocation allowed) ----------------
__device__ float g_Z[TOT];
__device__ float g_K[TOT];
__device__ float g_Y1[TOT];
__device__ float g_Y2[TOT];
__device__ float g_Y3[TOT];
__device__ float g_ZACC[TOT];

__device__ float g_W0t[3 * 80 * 128];
__device__ float g_W1t[9 * 128 * 128];
__device__ float g_W2t[9 * 128 * 128];
__device__ float g_W3t[1 * 128 * 128];

__device__ float g_sum1[128], g_ssq1[128], g_m1[128], g_r1[128];
__device__ float g_sum2[128], g_ssq2[128], g_m2[128], g_r2[128];
__device__ float g_sum3[128], g_ssq3[128], g_m3[128], g_r3[128];

// ---------------- helpers ----------------
__global__ void init_stats_kernel() {
    int c = threadIdx.x;
    if (c < 128) {
        g_sum1[c] = 0.f; g_ssq1[c] = 0.f;
        g_sum2[c] = 0.f; g_ssq2[c] = 0.f;
        g_sum3[c] = 0.f; g_ssq3[c] = 0.f;
    }
}

// dst[(k*CI + ci)*CO + co] = src[(co*CI + ci)*NK + k]
__global__ void transpose_w_kernel(const float* __restrict__ src, float* __restrict__ dst,
                                   int CO, int CI, int NK) {
    int idx = blockIdx.x * 256 + threadIdx.x;
    int tot = CO * CI * NK;
    if (idx < tot) {
        int co = idx / (CI * NK);
        int r  = idx % (CI * NK);
        int ci = r / NK;
        int k  = r % NK;
        dst[(k * CI + ci) * CO + co] = src[idx];
    }
}

// finalize per-channel mean/rstd from sums (biased var), then reset sums.
__global__ void finalize_stats_kernel(float* s1, float* q1, float* m1, float* r1,
                                      float* s2, float* q2, float* m2, float* r2) {
    int c = threadIdx.x;
    if (c >= 128) return;
    const float invN = 1.0f / NELEM;
    float m = s1[c] * invN;
    float v = q1[c] * invN - m * m;
    m1[c] = m; r1[c] = rsqrtf(v + 1e-5f);
    s1[c] = 0.f; q1[c] = 0.f;
    if (s2 != nullptr) {
        m = s2[c] * invN;
        v = q2[c] * invN - m * m;
        m2[c] = m; r2[c] = rsqrtf(v + 1e-5f);
        s2[c] = 0.f; q2[c] = 0.f;
    }
}

// Z = relu((Y - m)*r)   (elementwise over (c,b,t<500))
__global__ void bn_relu_kernel(const float* __restrict__ Y,
                               const float* __restrict__ m, const float* __restrict__ r,
                               float* __restrict__ Z) {
    int row = blockIdx.x;          // row = c*128 + b
    int c = row >> 7;
    float mm = m[c], rr = r[c];
    int base = row * TP;
    for (int t = threadIdx.x; t < TLEN; t += 128)
        Z[base + t] = fmaxf((Y[base + t] - mm) * rr, 0.f);
}

// k = relu(bn(Y2) + relu(bn(Y3)));  K = k;  RK4 accumulator updates.
// mode 0: ZACC = Z + w*k      (first eval of a step)
// mode 1: ZACC += w*k
// mode 2: Zout = ZACC + w*k   (last eval: produce next z)
__global__ void combine_kernel(const float* __restrict__ Y2, const float* __restrict__ Y3,
                               const float* __restrict__ m2, const float* __restrict__ r2,
                               const float* __restrict__ m3, const float* __restrict__ r3,
                               const float* __restrict__ Z, float* __restrict__ K,
                               float* __restrict__ ZA, float* __restrict__ Zout,
                               float wgt, int mode) {
    int row = blockIdx.x;
    int c = row >> 7;
    float mm2 = m2[c], rr2 = r2[c], mm3 = m3[c], rr3 = r3[c];
    int base = row * TP;
    for (int t = threadIdx.x; t < TLEN; t += 128) {
        int i = base + t;
        float y3n = fmaxf((Y3[i] - mm3) * rr3, 0.f);
        float k = fmaxf((Y2[i] - mm2) * rr2 + y3n, 0.f);
        K[i] = k;
        if (mode == 0)      ZA[i] = Z[i] + wgt * k;
        else if (mode == 1) ZA[i] = ZA[i] + wgt * k;
        else                Zout[i] = ZA[i] + wgt * k;
    }
}

// ---------------- tiled conv (implicit GEMM) ----------------
// out[co][b][t] = sum_{ci,k} wt[k][ci][co] * a[ci][b][t + k - R]
// where a = (in [+ alpha*in2]) then optional relu(bn(.)), zero outside t in [0,500).
// Tile: 128 co x 128 t per block; thread = 8co x 8t. grid = (4 t-tiles, 128 b).
template <int NTAPS, int CIN, bool RAW>
__global__ __launch_bounds__(256, 2) void conv_kernel(
    const float* __restrict__ in, const float* __restrict__ in2, float alpha,
    const float* __restrict__ wt,
    const float* __restrict__ bnm, const float* __restrict__ bnr,
    float* __restrict__ out, float* __restrict__ osum, float* __restrict__ ossq) {

    constexpr int R  = NTAPS / 2;
    constexpr int AW = 128 + NTAPS - 1;   // <= 136
    constexpr int CK = 8;

    __shared__ float As[CK][136];
    __shared__ float Ws[NTAPS][CK][128];

    const int t0  = blockIdx.x * 128;
    const int b   = blockIdx.y;
    const int tid = threadIdx.x;
    const int cid = tid & 15;     // co group
    const int tgi = tid >> 4;     // t group
    const int co0 = cid * 8;
    const int tl0 = tgi * 8;

    float acc[8][8];
#pragma unroll
    for (int i = 0; i < 8; i++)
#pragma unroll
        for (int j = 0; j < 8; j++) acc[i][j] = 0.f;

    const bool has2 = (in2 != nullptr);
    const bool hasbn = (bnm != nullptr);

#pragma unroll 1
    for (int cc = 0; cc < CIN / CK; ++cc) {
        __syncthreads();
        // stage A slice: CK channels x AW columns
        for (int idx = tid; idx < CK * AW; idx += 256) {
            int ci = idx / AW;
            int j  = idx % AW;
            int gc = t0 - R + j;
            float v = 0.f;
            if (gc >= 0 && gc < TLEN) {
                int cg = cc * CK + ci;
                int off;
                if (RAW) off = (b * CIN + cg) * TLEN + gc;      // x: [B][CIN][T]
                else     off = (cg * BB + b) * TP + gc;          // padded feature layout
                v = in[off];
                if (has2) v += alpha * in2[off];
                if (hasbn) v = fmaxf((v - bnm[cg]) * bnr[cg], 0.f);
            }
            As[ci][j] = v;
        }
        // stage W chunk: all taps, CK channels, 128 co (co contiguous)
        for (int idx = tid; idx < NTAPS * CK * 128; idx += 256) {
            int k  = idx / (CK * 128);
            int r  = idx % (CK * 128);
            int ci = r >> 7;
            int co = r & 127;
            Ws[k][ci][co] = wt[(k * CIN + cc * CK + ci) * 128 + co];
        }
        __syncthreads();

#pragma unroll 1
        for (int ci = 0; ci < CK; ++ci) {
            float aw[8 + NTAPS - 1];
#pragma unroll
            for (int q = 0; q < 8 + NTAPS - 1; ++q) aw[q] = As[ci][tl0 + q];
#pragma unroll
            for (int k = 0; k < NTAPS; ++k) {
                float w8[8];
#pragma unroll
                for (int i = 0; i < 8; i++) w8[i] = Ws[k][ci][co0 + i];
#pragma unroll
                for (int i = 0; i < 8; i++)
#pragma unroll
                    for (int j = 0; j < 8; j++)
                        acc[i][j] = fmaf(w8[i], aw[k + j], acc[i][j]);
            }
        }
    }

    // store + per-channel partial stats
    float s[8], q[8];
#pragma unroll
    for (int i = 0; i < 8; i++) { s[i] = 0.f; q[i] = 0.f; }

#pragma unroll
    for (int i = 0; i < 8; i++) {
        int co = co0 + i;
        int rowoff = (co * BB + b) * TP;
#pragma unroll
        for (int j = 0; j < 8; j++) {
            int tg = t0 + tl0 + j;
            if (tg < TLEN) {
                float v = acc[i][j];
                out[rowoff + tg] = v;
                s[i] += v;
                q[i] += v * v;
            }
        }
    }
    // lanes l and l^16 share the same co set (cid = tid & 15)
#pragma unroll
    for (int i = 0; i < 8; i++) {
        s[i] += __shfl_xor_sync(0xffffffffu, s[i], 16);
        q[i] += __shfl_xor_sync(0xffffffffu, q[i], 16);
    }
    if ((tid & 31) < 16) {
#pragma unroll
        for (int i = 0; i < 8; i++) {
            atomicAdd(&osum[co0 + i], s[i]);
            atomicAdd(&ossq[co0 + i], q[i]);
        }
    }
}

// ---------------- pool + head ----------------
__global__ void pool_head_kernel(const float* __restrict__ Z,
                                 const float* __restrict__ ow, const float* __restrict__ ob,
                                 float* __restrict__ out) {
    __shared__ float feat[128];
    int b = blockIdx.x;
    int c = threadIdx.x;
    const float* row = Z + (c * BB + b) * TP;
    float sum = 0.f;
    for (int t = 0; t < TLEN; t++) sum += row[t];
    feat[c] = sum * (1.0f / (float)TLEN);
    __syncthreads();
    if (c < NLAB) {
        float o = ob[c];
        for (int k = 0; k < 128; k++) o = fmaf(feat[k], ow[c * 128 + k], o);
        out[b * NLAB + c] = o;
    }
}

// ---------------- launch ----------------
extern "C" void kernel_launch(void* const* d_in, const int* in_sizes, int n_in,
                              void* d_out, int out_size) {
    const float* x   = (const float*)d_in[0];   // [128][80][500]
    const float* w0  = (const float*)d_in[1];   // [128][80][3][1]
    const float* w1  = (const float*)d_in[2];   // [128][128][9][1]
    const float* w2  = (const float*)d_in[3];   // [128][128][9][1]
    const float* w3  = (const float*)d_in[4];   // [128][128][1][1]
    const float* ow  = (const float*)d_in[5];   // [35][128]
    const float* ob  = (const float*)d_in[6];   // [35]
    float* out = (float*)d_out;

    float *pZ, *pK, *pY1, *pY2, *pY3, *pZA;
    float *pW0, *pW1, *pW2, *pW3;
    float *ps1, *pq1, *pm1, *pr1, *ps2, *pq2, *pm2, *pr2, *ps3, *pq3, *pm3, *pr3;
    cudaGetSymbolAddress((void**)&pZ, g_Z);
    cudaGetSymbolAddress((void**)&pK, g_K);
    cudaGetSymbolAddress((void**)&pY1, g_Y1);
    cudaGetSymbolAddress((void**)&pY2, g_Y2);
    cudaGetSymbolAddress((void**)&pY3, g_Y3);
    cudaGetSymbolAddress((void**)&pZA, g_ZACC);
    cudaGetSymbolAddress((void**)&pW0, g_W0t);
    cudaGetSymbolAddress((void**)&pW1, g_W1t);
    cudaGetSymbolAddress((void**)&pW2, g_W2t);
    cudaGetSymbolAddress((void**)&pW3, g_W3t);
    cudaGetSymbolAddress((void**)&ps1, g_sum1); cudaGetSymbolAddress((void**)&pq1, g_ssq1);
    cudaGetSymbolAddress((void**)&pm1, g_m1);   cudaGetSymbolAddress((void**)&pr1, g_r1);
    cudaGetSymbolAddress((void**)&ps2, g_sum2); cudaGetSymbolAddress((void**)&pq2, g_ssq2);
    cudaGetSymbolAddress((void**)&pm2, g_m2);   cudaGetSymbolAddress((void**)&pr2, g_r2);
    cudaGetSymbolAddress((void**)&ps3, g_sum3); cudaGetSymbolAddress((void**)&pq3, g_ssq3);
    cudaGetSymbolAddress((void**)&pm3, g_m3);   cudaGetSymbolAddress((void**)&pr3, g_r3);

    const float dt = 1.0f / 4.0f;           // INTEGRATION_TIME / NSTEPS
    dim3 cgrid(4, 128);                     // 4 t-tiles x 128 batches
    const int rows = 128 * 128;             // (c, b) rows

    init_stats_kernel<<<1, 128>>>();

    // transpose weights to [k][ci][co]
    transpose_w_kernel<<<(128 * 80 * 3 + 255) / 256, 256>>>(w0, pW0, 128, 80, 3);
    transpose_w_kernel<<<(128 * 128 * 9 + 255) / 256, 256>>>(w1, pW1, 128, 128, 9);
    transpose_w_kernel<<<(128 * 128 * 9 + 255) / 256, 256>>>(w2, pW2, 128, 128, 9);
    transpose_w_kernel<<<(128 * 128 * 1 + 255) / 256, 256>>>(w3, pW3, 128, 128, 1);

    // conv0 + BN + relu -> Z
    conv_kernel<3, 80, true><<<cgrid, 256>>>(x, nullptr, 0.f, pW0, nullptr, nullptr,
                                             pY1, ps1, pq1);
    finalize_stats_kernel<<<1, 128>>>(ps1, pq1, pm1, pr1, nullptr, nullptr, nullptr, nullptr);
    bn_relu_kernel<<<rows, 128>>>(pY1, pm1, pr1, pZ);

    // 4 RK4 steps x 4 odefunc evals
    for (int step = 0; step < 4; ++step) {
        for (int e = 0; e < 4; ++e) {
            float alpha = (e == 0) ? 0.f : (e == 3 ? dt : 0.5f * dt);
            const float* in2 = (e == 0) ? nullptr : (const float*)pK;

            // conv1(z + alpha*k)  -> Y1 (+stats1)
            conv_kernel<9, 128, false><<<cgrid, 256>>>(pZ, in2, alpha, pW1,
                                                       nullptr, nullptr, pY1, ps1, pq1);
            // conv3(z + alpha*k)  -> Y3 (+stats3)
            conv_kernel<1, 128, false><<<cgrid, 256>>>(pZ, in2, alpha, pW3,
                                                       nullptr, nullptr, pY3, ps3, pq3);
            finalize_stats_kernel<<<1, 128>>>(ps1, pq1, pm1, pr1, ps3, pq3, pm3, pr3);

            // conv2(relu(bn(Y1))) -> Y2 (+stats2)
            conv_kernel<9, 128, false><<<cgrid, 256>>>(pY1, nullptr, 0.f, pW2,
                                                       pm1, pr1, pY2, ps2, pq2);
            finalize_stats_kernel<<<1, 128>>>(ps2, pq2, pm2, pr2, nullptr, nullptr, nullptr, nullptr);

            // k = relu(bn(Y2) + relu(bn(Y3)));  RK4 accumulation
            float wgt = (dt / 6.0f) * ((e == 0 || e == 3) ? 1.0f : 2.0f);
            int mode = (e == 0) ? 0 : (e == 3 ? 2 : 1);
            combine_kernel<<<rows, 128>>>(pY2, pY3, pm2, pr2, pm3, pr3,
                                          pZ, pK, pZA, pZ, wgt, mode);
        }
    }

    // global average pool + linear head
    pool_head_kernel<<<128, 128>>>(pZ, ow, ob, out);
}

// round 5
// speedup vs baseline: 4.3488x; 4.3371x over previous
#include <cuda_runtime.h>
#include <cuda_bf16.h>
#include <cstdint>
#include <math.h>

#define BBATCH 128
#define TLEN   500
#define NLAB   35
#define FSZ    (128*500*128)     // [b][t][c] feature tensor
#define NELEM  64000.0f

// ---------- device scratch ----------
__device__ float g_X[FSZ];
__device__ float g_Z[FSZ];
__device__ float g_K[FSZ];
__device__ float g_Y1[FSZ];
__device__ float g_Y2[FSZ];
__device__ float g_Y3[FSZ];
__device__ float g_ZA[FSZ];

// pre-split weight images: [tap][2 splits][128 co][136 ci] bf16
__device__ __nv_bfloat16 g_W0p[3*2*128*136];
__device__ __nv_bfloat16 g_W1p[9*2*128*136];
__device__ __nv_bfloat16 g_W2p[9*2*128*136];
__device__ __nv_bfloat16 g_W3p[1*2*128*136];

__device__ float g_sum1[128], g_ssq1[128], g_m1[128], g_r1[128];
__device__ float g_sum2[128], g_ssq2[128], g_m2[128], g_r2[128];
__device__ float g_sum3[128], g_ssq3[128], g_m3[128], g_r3[128];

// ---------- helpers ----------
__device__ __forceinline__ uint32_t smem_u32(const void* p) {
    uint32_t a;
    asm("{ .reg .u64 t; cvta.to.shared.u64 t, %1; cvt.u32.u64 %0, t; }" : "=r"(a) : "l"(p));
    return a;
}
__device__ __forceinline__ void cp_async16(uint32_t dst, const void* src) {
    asm volatile("cp.async.cg.shared.global [%0], [%1], 16;" :: "r"(dst), "l"(src));
}
#define CP_COMMIT() asm volatile("cp.async.commit_group;" ::: "memory")
#define CP_WAIT(n)  asm volatile("cp.async.wait_group %0;" :: "n"(n) : "memory")

__device__ __forceinline__ void mma_bf16(float* d, const uint32_t* a, const uint32_t* b) {
    asm volatile("mma.sync.aligned.m16n8k16.row.col.f32.bf16.bf16.f32 "
        "{%0,%1,%2,%3}, {%4,%5,%6,%7}, {%8,%9}, {%0,%1,%2,%3};"
        : "+f"(d[0]), "+f"(d[1]), "+f"(d[2]), "+f"(d[3])
        : "r"(a[0]), "r"(a[1]), "r"(a[2]), "r"(a[3]), "r"(b[0]), "r"(b[1]));
}

// ---------- small kernels ----------
__global__ void init_stats_kernel() {
    int c = threadIdx.x;
    if (c < 128) {
        g_sum1[c]=0.f; g_ssq1[c]=0.f; g_sum2[c]=0.f; g_ssq2[c]=0.f; g_sum3[c]=0.f; g_ssq3[c]=0.f;
    }
}

// src [128 co][CIR][NK] -> img [tap][split][co][136]
__global__ void prep_w_kernel(const float* __restrict__ src, __nv_bfloat16* __restrict__ img,
                              int CIR, int NK) {
    int idx = blockIdx.x * 256 + threadIdx.x;
    int tot = NK * 128 * 136;
    if (idx >= tot) return;
    int tap = idx / (128 * 136);
    int rem = idx - tap * 128 * 136;
    int co = rem / 136, ci = rem - co * 136;
    float v = (ci < CIR) ? src[(co * CIR + ci) * NK + tap] : 0.f;
    __nv_bfloat16 h = __float2bfloat16(v);
    float l = v - __bfloat162float(h);
    img[(tap*2 + 0)*128*136 + co*136 + ci] = h;
    img[(tap*2 + 1)*128*136 + co*136 + ci] = __float2bfloat16(l);
}

// x[b][80][500] -> X[b][t][c] (c 80..127 zero)
__global__ void xpose_kernel(const float* __restrict__ x, float* __restrict__ X) {
    int i = blockIdx.x * 256 + threadIdx.x;
    if (i >= FSZ) return;
    int c = i & 127, bt = i >> 7;
    int t = bt % TLEN, b = bt / TLEN;
    X[i] = (c < 80) ? x[(b * 80 + c) * TLEN + t] : 0.f;
}

__global__ void finalize_stats_kernel(float* s1, float* q1, float* m1, float* r1,
                                      float* s2, float* q2, float* m2, float* r2) {
    int c = threadIdx.x;
    if (c >= 128) return;
    const float invN = 1.0f / NELEM;
    float m = s1[c] * invN, v = q1[c] * invN - m * m;
    m1[c] = m; r1[c] = rsqrtf(v + 1e-5f); s1[c] = 0.f; q1[c] = 0.f;
    if (s2) {
        m = s2[c] * invN; v = q2[c] * invN - m * m;
        m2[c] = m; r2[c] = rsqrtf(v + 1e-5f); s2[c] = 0.f; q2[c] = 0.f;
    }
}

__global__ void bn_relu_kernel(const float* __restrict__ Y, const float* __restrict__ m,
                               const float* __restrict__ r, float* __restrict__ Z) {
    int i = blockIdx.x * 256 + threadIdx.x;
    if (i >= FSZ) return;
    int c = i & 127;
    Z[i] = fmaxf((Y[i] - m[c]) * r[c], 0.f);
}

__global__ void combine_kernel(const float* __restrict__ Y2, const float* __restrict__ Y3,
                               const float* __restrict__ m2, const float* __restrict__ r2,
                               const float* __restrict__ m3, const float* __restrict__ r3,
                               const float* __restrict__ Z, float* __restrict__ K,
                               float* __restrict__ ZA, float* __restrict__ Zout,
                               float wgt, int mode) {
    int i = blockIdx.x * 256 + threadIdx.x;
    if (i >= FSZ) return;
    int c = i & 127;
    float y3n = fmaxf((Y3[i] - m3[c]) * r3[c], 0.f);
    float k = fmaxf((Y2[i] - m2[c]) * r2[c] + y3n, 0.f);
    K[i] = k;
    if (mode == 0)      ZA[i] = Z[i] + wgt * k;
    else if (mode == 1) ZA[i] = ZA[i] + wgt * k;
    else                Zout[i] = ZA[i] + wgt * k;
}

__global__ void pool_head_kernel(const float* __restrict__ Z, const float* __restrict__ ow,
                                 const float* __restrict__ ob, float* __restrict__ out) {
    __shared__ float feat[128];
    int b = blockIdx.x, c = threadIdx.x;
    float s = 0.f;
    for (int t = 0; t < TLEN; t++) s += Z[((b * TLEN + t) << 7) + c];
    feat[c] = s * (1.0f / (float)TLEN);
    __syncthreads();
    if (c < NLAB) {
        float o = ob[c];
        for (int k = 0; k < 128; k++) o = fmaf(feat[k], ow[c * 128 + k], o);
        out[b * NLAB + c] = o;
    }
}

// ---------- mma.sync conv kernel ----------
// CTA: batch b, 128 co x 125 t outputs. B smem: 136 t-rows x 128 ci (bf16 hi/lo),
// row stride 272B. A (weights) cp.async double-buffered per tap.
// Output t0+j accumulates tap k from B row (j + k).
#define NB     136
#define ROWB   272
#define BH_OFF 0
#define BL_OFF (NB*ROWB)          // 36992
#define A_OFF  (2*NB*ROWB)        // 73984
#define A_TAPB 69632              // per-tap A bytes (2 splits x 128 rows x 272)
#define SMEM_SZ (A_OFF + 2*A_TAPB)  // 213248

template <int NTAPS>
__global__ __launch_bounds__(256, 1)
void conv_mma_kernel(const float* __restrict__ in, const float* __restrict__ in2, float alpha,
                     const __nv_bfloat16* __restrict__ wimg,
                     const float* __restrict__ bnm, const float* __restrict__ bnr,
                     float* __restrict__ out, float* __restrict__ osum, float* __restrict__ ossq) {
    constexpr int R = NTAPS / 2;
    extern __shared__ char smem[];
    const uint32_t sb = smem_u32(smem);
    const int tid = threadIdx.x;
    const int t0 = blockIdx.x * 125;
    const int b  = blockIdx.y;

    const bool h2 = (in2 != nullptr), hbn = (bnm != nullptr);

    // ---- stage B: 136 rows x 64 bf16-pairs per split ----
    for (int idx = tid; idx < NB * 64; idx += 256) {
        int j = idx >> 6, pr = idx & 63;
        int u = t0 - R + j;
        float v0 = 0.f, v1 = 0.f;
        if (u >= 0 && u < TLEN) {
            const float* p = in + ((b * TLEN + u) << 7) + pr * 2;
            v0 = p[0]; v1 = p[1];
            if (h2) {
                const float* q = in2 + ((b * TLEN + u) << 7) + pr * 2;
                v0 += alpha * q[0]; v1 += alpha * q[1];
            }
            if (hbn) {
                int c = pr * 2;
                v0 = fmaxf((v0 - bnm[c]) * bnr[c], 0.f);
                v1 = fmaxf((v1 - bnm[c + 1]) * bnr[c + 1], 0.f);
            }
        }
        __nv_bfloat16 h0 = __float2bfloat16(v0);
        __nv_bfloat16 h1 = __float2bfloat16(v1);
        __nv_bfloat16 l0 = __float2bfloat16(v0 - __bfloat162float(h0));
        __nv_bfloat16 l1 = __float2bfloat16(v1 - __bfloat162float(h1));
        __nv_bfloat162 hh; hh.x = h0; hh.y = h1;
        __nv_bfloat162 ll; ll.x = l0; ll.y = l1;
        *(__nv_bfloat162*)(smem + BH_OFF + j * ROWB + pr * 4) = hh;
        *(__nv_bfloat162*)(smem + BL_OFF + j * ROWB + pr * 4) = ll;
    }

    // ---- prefetch A tap 0 ----
    {
        const char* src = (const char*)wimg;
        uint32_t dst = sb + A_OFF;
#pragma unroll
        for (int i = 0; i < 17; i++) cp_async16(dst + (tid + i * 256) * 16, src + (tid + i * 256) * 16);
        CP_COMMIT();
    }
    __syncthreads();   // B ready

    // warp layout: 4 (co) x 2 (t)
    const int wid = tid >> 5, lane = tid & 31;
    const int co_w = (wid >> 1) * 32;
    const int t_w  = (wid & 1) * 64;
    const int g  = lane >> 2;      // group
    const int tq = lane & 3;       // thread-in-group

    float acc[2][8][4];
#pragma unroll
    for (int mt = 0; mt < 2; mt++)
#pragma unroll
        for (int nt = 0; nt < 8; nt++)
#pragma unroll
            for (int e = 0; e < 4; e++) acc[mt][nt][e] = 0.f;

#pragma unroll 1
    for (int tap = 0; tap < NTAPS; tap++) {
        const int buf = tap & 1;
        if (tap + 1 < NTAPS) {
            const char* src = (const char*)wimg + (size_t)(tap + 1) * A_TAPB;
            uint32_t dst = sb + A_OFF + ((tap + 1) & 1) * A_TAPB;
#pragma unroll
            for (int i = 0; i < 17; i++) cp_async16(dst + (tid + i * 256) * 16, src + (tid + i * 256) * 16);
            CP_COMMIT();
            CP_WAIT(1);
        } else {
            CP_WAIT(0);
        }
        __syncthreads();

        const char* Ah = smem + A_OFF + buf * A_TAPB;
        const char* Al = Ah + (A_TAPB / 2);

#pragma unroll 1
        for (int kc = 0; kc < 8; kc++) {
            uint32_t ah[2][4], al[2][4];
            const int kbyte = kc * 32 + tq * 4;
#pragma unroll
            for (int mt = 0; mt < 2; mt++) {
                int r = (co_w + mt * 16 + g) * ROWB + kbyte;
                ah[mt][0] = *(const uint32_t*)(Ah + r);
                ah[mt][1] = *(const uint32_t*)(Ah + r + 8 * ROWB);
                ah[mt][2] = *(const uint32_t*)(Ah + r + 16);
                ah[mt][3] = *(const uint32_t*)(Ah + r + 8 * ROWB + 16);
                al[mt][0] = *(const uint32_t*)(Al + r);
                al[mt][1] = *(const uint32_t*)(Al + r + 8 * ROWB);
                al[mt][2] = *(const uint32_t*)(Al + r + 16);
                al[mt][3] = *(const uint32_t*)(Al + r + 8 * ROWB + 16);
            }
#pragma unroll
            for (int nt = 0; nt < 8; nt++) {
                const int trow = t_w + nt * 8 + g + tap;
                const int boff = trow * ROWB + kbyte;
                uint32_t bh[2], bl[2];
                bh[0] = *(const uint32_t*)(smem + BH_OFF + boff);
                bh[1] = *(const uint32_t*)(smem + BH_OFF + boff + 16);
                bl[0] = *(const uint32_t*)(smem + BL_OFF + boff);
                bl[1] = *(const uint32_t*)(smem + BL_OFF + boff + 16);
                mma_bf16(acc[0][nt], ah[0], bh);
                mma_bf16(acc[1][nt], ah[1], bh);
                mma_bf16(acc[0][nt], ah[0], bl);
                mma_bf16(acc[1][nt], ah[1], bl);
                mma_bf16(acc[0][nt], al[0], bh);
                mma_bf16(acc[1][nt], al[1], bh);
            }
        }
        __syncthreads();   // protect A buffers from next prefetch
    }

    // ---- epilogue: frags -> smem [128 t][132 co stride] -> coalesced stores + stats ----
    float* Ts = (float*)smem;
#pragma unroll
    for (int mt = 0; mt < 2; mt++)
#pragma unroll
        for (int nt = 0; nt < 8; nt++) {
            int co = co_w + mt * 16 + g;
            int t  = t_w + nt * 8 + tq * 2;
            Ts[t * 132 + co]            = acc[mt][nt][0];
            Ts[(t + 1) * 132 + co]      = acc[mt][nt][1];
            Ts[t * 132 + co + 8]        = acc[mt][nt][2];
            Ts[(t + 1) * 132 + co + 8]  = acc[mt][nt][3];
        }
    __syncthreads();

    {
        int c = tid & 127;
        float s = 0.f, q = 0.f;
        for (int t = (tid >> 7); t < 125; t += 2) {
            float v = Ts[t * 132 + c];
            s += v; q += v * v;
            out[((b * TLEN + t0 + t) << 7) + c] = v;
        }
        atomicAdd(&osum[c], s);
        atomicAdd(&ossq[c], q);
    }
}

// ---------- launch ----------
extern "C" void kernel_launch(void* const* d_in, const int* in_sizes, int n_in,
                              void* d_out, int out_size) {
    const float* x  = (const float*)d_in[0];
    const float* w0 = (const float*)d_in[1];
    const float* w1 = (const float*)d_in[2];
    const float* w2 = (const float*)d_in[3];
    const float* w3 = (const float*)d_in[4];
    const float* ow = (const float*)d_in[5];
    const float* ob = (const float*)d_in[6];
    float* out = (float*)d_out;

    cudaFuncSetAttribute(conv_mma_kernel<9>, cudaFuncAttributeMaxDynamicSharedMemorySize, SMEM_SZ);
    cudaFuncSetAttribute(conv_mma_kernel<3>, cudaFuncAttributeMaxDynamicSharedMemorySize, SMEM_SZ);
    cudaFuncSetAttribute(conv_mma_kernel<1>, cudaFuncAttributeMaxDynamicSharedMemorySize, SMEM_SZ);

    float *pX,*pZ,*pK,*pY1,*pY2,*pY3,*pZA;
    __nv_bfloat16 *pW0,*pW1,*pW2,*pW3;
    float *ps1,*pq1,*pm1,*pr1,*ps2,*pq2,*pm2,*pr2,*ps3,*pq3,*pm3,*pr3;
    cudaGetSymbolAddress((void**)&pX,  g_X);
    cudaGetSymbolAddress((void**)&pZ,  g_Z);
    cudaGetSymbolAddress((void**)&pK,  g_K);
    cudaGetSymbolAddress((void**)&pY1, g_Y1);
    cudaGetSymbolAddress((void**)&pY2, g_Y2);
    cudaGetSymbolAddress((void**)&pY3, g_Y3);
    cudaGetSymbolAddress((void**)&pZA, g_ZA);
    cudaGetSymbolAddress((void**)&pW0, g_W0p);
    cudaGetSymbolAddress((void**)&pW1, g_W1p);
    cudaGetSymbolAddress((void**)&pW2, g_W2p);
    cudaGetSymbolAddress((void**)&pW3, g_W3p);
    cudaGetSymbolAddress((void**)&ps1, g_sum1); cudaGetSymbolAddress((void**)&pq1, g_ssq1);
    cudaGetSymbolAddress((void**)&pm1, g_m1);   cudaGetSymbolAddress((void**)&pr1, g_r1);
    cudaGetSymbolAddress((void**)&ps2, g_sum2); cudaGetSymbolAddress((void**)&pq2, g_ssq2);
    cudaGetSymbolAddress((void**)&pm2, g_m2);   cudaGetSymbolAddress((void**)&pr2, g_r2);
    cudaGetSymbolAddress((void**)&ps3, g_sum3); cudaGetSymbolAddress((void**)&pq3, g_ssq3);
    cudaGetSymbolAddress((void**)&pm3, g_m3);   cudaGetSymbolAddress((void**)&pr3, g_r3);

    const float dt = 0.25f;
    dim3 cgrid(4, 128);
    const int EW = (FSZ + 255) / 256;

    init_stats_kernel<<<1, 128>>>();
    prep_w_kernel<<<(3*128*136 + 255)/256, 256>>>(w0, pW0, 80, 3);
    prep_w_kernel<<<(9*128*136 + 255)/256, 256>>>(w1, pW1, 128, 9);
    prep_w_kernel<<<(9*128*136 + 255)/256, 256>>>(w2, pW2, 128, 9);
    prep_w_kernel<<<(1*128*136 + 255)/256, 256>>>(w3, pW3, 128, 1);
    xpose_kernel<<<EW, 256>>>(x, pX);

    // conv0 + BN + relu -> Z
    conv_mma_kernel<3><<<cgrid, 256, SMEM_SZ>>>(pX, nullptr, 0.f, pW0,
                                                nullptr, nullptr, pY1, ps1, pq1);
    finalize_stats_kernel<<<1, 128>>>(ps1, pq1, pm1, pr1, nullptr, nullptr, nullptr, nullptr);
    bn_relu_kernel<<<EW, 256>>>(pY1, pm1, pr1, pZ);

    for (int step = 0; step < 4; ++step) {
        for (int e = 0; e < 4; ++e) {
            float alpha = (e == 0) ? 0.f : (e == 3 ? dt : 0.5f * dt);
            const float* in2 = (e == 0) ? nullptr : (const float*)pK;

            conv_mma_kernel<9><<<cgrid, 256, SMEM_SZ>>>(pZ, in2, alpha, pW1,
                                                        nullptr, nullptr, pY1, ps1, pq1);
            conv_mma_kernel<1><<<cgrid, 256, SMEM_SZ>>>(pZ, in2, alpha, pW3,
                                                        nullptr, nullptr, pY3, ps3, pq3);
            finalize_stats_kernel<<<1, 128>>>(ps1, pq1, pm1, pr1, ps3, pq3, pm3, pr3);

            conv_mma_kernel<9><<<cgrid, 256, SMEM_SZ>>>(pY1, nullptr, 0.f, pW2,
                                                        pm1, pr1, pY2, ps2, pq2);
            finalize_stats_kernel<<<1, 128>>>(ps2, pq2, pm2, pr2, nullptr, nullptr, nullptr, nullptr);

            float wgt = (dt / 6.0f) * ((e == 0 || e == 3) ? 1.0f : 2.0f);
            int mode = (e == 0) ? 0 : (e == 3 ? 2 : 1);
            combine_kernel<<<EW, 256>>>(pY2, pY3, pm2, pr2, pm3, pr3,
                                        pZ, pK, pZA, pZ, wgt, mode);
        }
    }

    pool_head_kernel<<<128, 128>>>(pZ, ow, ob, out);
}

// round 6
// speedup vs baseline: 9.1399x; 2.1017x over previous
#include <cuda_runtime.h>
#include <cuda_fp16.h>
#include <cstdint>
#include <math.h>

#define BBATCH 128
#define TLEN   500
#define NLAB   35
#define FSZ    (128*500*128)     // [b][t][c] feature tensor
#define NELEM  64000.0f

// ---------- device scratch ----------
__device__ float g_X[FSZ];
__device__ float g_Z[FSZ];
__device__ float g_K[FSZ];
__device__ float g_Y1[FSZ];
__device__ float g_Y2[FSZ];
__device__ float g_Y3[FSZ];
__device__ float g_ZA[FSZ];

// fp16 weight images: [tap][128 co][136 ci]
__device__ __half g_W0p[3*128*136];
__device__ __half g_W1p[9*128*136];
__device__ __half g_W2p[9*128*136];
__device__ __half g_W3p[1*128*136];

__device__ float g_sum1[128], g_ssq1[128], g_m1[128], g_r1[128];
__device__ float g_sum2[128], g_ssq2[128], g_m2[128], g_r2[128];
__device__ float g_sum3[128], g_ssq3[128], g_m3[128], g_r3[128];

// ---------- helpers ----------
__device__ __forceinline__ uint32_t smem_u32(const void* p) {
    uint32_t a;
    asm("{ .reg .u64 t; cvta.to.shared.u64 t, %1; cvt.u32.u64 %0, t; }" : "=r"(a) : "l"(p));
    return a;
}
__device__ __forceinline__ void cp_async16(uint32_t dst, const void* src) {
    asm volatile("cp.async.cg.shared.global [%0], [%1], 16;" :: "r"(dst), "l"(src));
}
#define CP_COMMIT() asm volatile("cp.async.commit_group;" ::: "memory")
#define CP_WAIT(n)  asm volatile("cp.async.wait_group %0;" :: "n"(n) : "memory")

__device__ __forceinline__ void ldsm_x4(uint32_t* r, uint32_t addr) {
    asm volatile("ldmatrix.sync.aligned.m8n8.x4.shared.b16 {%0,%1,%2,%3}, [%4];"
        : "=r"(r[0]), "=r"(r[1]), "=r"(r[2]), "=r"(r[3]) : "r"(addr));
}
__device__ __forceinline__ void mma_f16(float* d, const uint32_t* a, uint32_t b0, uint32_t b1) {
    asm volatile("mma.sync.aligned.m16n8k16.row.col.f32.f16.f16.f32 "
        "{%0,%1,%2,%3}, {%4,%5,%6,%7}, {%8,%9}, {%0,%1,%2,%3};"
        : "+f"(d[0]), "+f"(d[1]), "+f"(d[2]), "+f"(d[3])
        : "r"(a[0]), "r"(a[1]), "r"(a[2]), "r"(a[3]), "r"(b0), "r"(b1));
}

// ---------- small kernels ----------
__global__ void init_stats_kernel() {
    int c = threadIdx.x;
    if (c < 128) {
        g_sum1[c]=0.f; g_ssq1[c]=0.f; g_sum2[c]=0.f; g_ssq2[c]=0.f; g_sum3[c]=0.f; g_ssq3[c]=0.f;
    }
}

// src [128 co][CIR][NK] -> img [tap][co][136] fp16
__global__ void prep_w_kernel(const float* __restrict__ src, __half* __restrict__ img,
                              int CIR, int NK) {
    int idx = blockIdx.x * 256 + threadIdx.x;
    int tot = NK * 128 * 136;
    if (idx >= tot) return;
    int tap = idx / (128 * 136);
    int rem = idx - tap * 128 * 136;
    int co = rem / 136, ci = rem - co * 136;
    float v = (ci < CIR) ? src[(co * CIR + ci) * NK + tap] : 0.f;
    img[idx] = __float2half_rn(v);
}

// x[b][80][500] -> X[b][t][c]
__global__ void xpose_kernel(const float* __restrict__ x, float* __restrict__ X) {
    int i = blockIdx.x * 256 + threadIdx.x;
    if (i >= FSZ) return;
    int c = i & 127, bt = i >> 7;
    int t = bt % TLEN, b = bt / TLEN;
    X[i] = (c < 80) ? x[(b * 80 + c) * TLEN + t] : 0.f;
}

__global__ void finalize_stats_kernel(float* s1, float* q1, float* m1, float* r1,
                                      float* s2, float* q2, float* m2, float* r2) {
    int c = threadIdx.x;
    if (c >= 128) return;
    const float invN = 1.0f / NELEM;
    float m = s1[c] * invN, v = q1[c] * invN - m * m;
    m1[c] = m; r1[c] = rsqrtf(v + 1e-5f); s1[c] = 0.f; q1[c] = 0.f;
    if (s2) {
        m = s2[c] * invN; v = q2[c] * invN - m * m;
        m2[c] = m; r2[c] = rsqrtf(v + 1e-5f); s2[c] = 0.f; q2[c] = 0.f;
    }
}

__global__ void bn_relu_kernel(const float* __restrict__ Y, const float* __restrict__ m,
                               const float* __restrict__ r, float* __restrict__ Z) {
    int i = blockIdx.x * 256 + threadIdx.x;
    if (i >= FSZ) return;
    int c = i & 127;
    Z[i] = fmaxf((Y[i] - m[c]) * r[c], 0.f);
}

__global__ void combine_kernel(const float* __restrict__ Y2, const float* __restrict__ Y3,
                               const float* __restrict__ m2, const float* __restrict__ r2,
                               const float* __restrict__ m3, const float* __restrict__ r3,
                               const float* __restrict__ Z, float* __restrict__ K,
                               float* __restrict__ ZA, float* __restrict__ Zout,
                               float wgt, int mode) {
    int i = blockIdx.x * 256 + threadIdx.x;
    if (i >= FSZ) return;
    int c = i & 127;
    float y3n = fmaxf((Y3[i] - m3[c]) * r3[c], 0.f);
    float k = fmaxf((Y2[i] - m2[c]) * r2[c] + y3n, 0.f);
    K[i] = k;
    if (mode == 0)      ZA[i] = Z[i] + wgt * k;
    else if (mode == 1) ZA[i] = ZA[i] + wgt * k;
    else                Zout[i] = ZA[i] + wgt * k;
}

__global__ void pool_head_kernel(const float* __restrict__ Z, const float* __restrict__ ow,
                                 const float* __restrict__ ob, float* __restrict__ out) {
    __shared__ float feat[128];
    int b = blockIdx.x, c = threadIdx.x;
    float s = 0.f;
    for (int t = 0; t < TLEN; t++) s += Z[((b * TLEN + t) << 7) + c];
    feat[c] = s * (1.0f / (float)TLEN);
    __syncthreads();
    if (c < NLAB) {
        float o = ob[c];
        for (int k = 0; k < 128; k++) o = fmaf(feat[k], ow[c * 128 + k], o);
        out[b * NLAB + c] = o;
    }
}

// ---------- mma.sync fp16 conv kernel ----------
// CTA: batch b, 128 co x 125 t outputs. B smem: 136 t-rows x 128 ci fp16 (row 272B).
// A (weights fp16) cp.async double-buffered per tap. Output t0+j <- tap k uses B row (j+k).
#define NB      136
#define ROWB    272
#define B_OFF   0
#define A_OFF   (NB*ROWB)         // 36992
#define A_TAPB  34816             // 128 rows x 272
#define SMEM_SZ (A_OFF + 2*A_TAPB)  // 106624
#define A_CHUNKS (A_TAPB/16)      // 2176

template <int NTAPS>
__global__ __launch_bounds__(256, 2)
void conv_mma_kernel(const float* __restrict__ in, const float* __restrict__ in2, float alpha,
                     const __half* __restrict__ wimg,
                     const float* __restrict__ bnm, const float* __restrict__ bnr,
                     float* __restrict__ out, float* __restrict__ osum, float* __restrict__ ossq) {
    constexpr int R = NTAPS / 2;
    extern __shared__ char smem[];
    const uint32_t sb = smem_u32(smem);
    const int tid = threadIdx.x;
    const int t0 = blockIdx.x * 125;
    const int b  = blockIdx.y;

    const bool h2 = (in2 != nullptr), hbn = (bnm != nullptr);

    // ---- stage B: 136 rows x 64 fp16-pairs ----
    for (int idx = tid; idx < NB * 64; idx += 256) {
        int j = idx >> 6, pr = idx & 63;
        int u = t0 - R + j;
        float v0 = 0.f, v1 = 0.f;
        if (u >= 0 && u < TLEN) {
            const float* p = in + ((b * TLEN + u) << 7) + pr * 2;
            v0 = p[0]; v1 = p[1];
            if (h2) {
                const float* q = in2 + ((b * TLEN + u) << 7) + pr * 2;
                v0 += alpha * q[0]; v1 += alpha * q[1];
            }
            if (hbn) {
                int c = pr * 2;
                v0 = fmaxf((v0 - bnm[c]) * bnr[c], 0.f);
                v1 = fmaxf((v1 - bnm[c + 1]) * bnr[c + 1], 0.f);
            }
        }
        *(__half2*)(smem + B_OFF + j * ROWB + pr * 4) = __floats2half2_rn(v0, v1);
    }

    // ---- prefetch A tap 0 ----
    for (int i = tid; i < A_CHUNKS; i += 256)
        cp_async16(sb + A_OFF + i * 16, (const char*)wimg + i * 16);
    CP_COMMIT();
    __syncthreads();   // B ready

    // warp layout: 2 (co) x 4 (t); warp tile 64co x 32t
    const int wid = tid >> 5, lane = tid & 31;
    const int co_w = (wid & 1) * 64;
    const int t_w  = (wid >> 1) * 32;
    const int g  = lane >> 2;
    const int tq = lane & 3;

    // ldmatrix lane addressing pieces
    const int a_row = lane & 15;            // + co tile
    const int a_kh  = (lane >> 4) * 16;     // k-half byte offset
    const int quad = lane >> 3;
    const int b_nl = (lane & 7) + ((quad >> 1) * 8);
    const int b_kh = (quad & 1) * 16;

    float acc[4][4][4];
#pragma unroll
    for (int mt = 0; mt < 4; mt++)
#pragma unroll
        for (int nt = 0; nt < 4; nt++)
#pragma unroll
            for (int e = 0; e < 4; e++) acc[mt][nt][e] = 0.f;

#pragma unroll 1
    for (int tap = 0; tap < NTAPS; tap++) {
        const int buf = tap & 1;
        if (tap + 1 < NTAPS) {
            const char* src = (const char*)wimg + (size_t)(tap + 1) * A_TAPB;
            uint32_t dst = sb + A_OFF + ((tap + 1) & 1) * A_TAPB;
            for (int i = tid; i < A_CHUNKS; i += 256) cp_async16(dst + i * 16, src + i * 16);
            CP_COMMIT();
            CP_WAIT(1);
        } else {
            CP_WAIT(0);
        }
        __syncthreads();

        const uint32_t Ab = sb + A_OFF + buf * A_TAPB;
        const uint32_t Bb = sb + B_OFF + (t_w + tap + b_nl) * ROWB + b_kh;

#pragma unroll
        for (int kc = 0; kc < 8; kc++) {
            uint32_t af[4][4];
#pragma unroll
            for (int mt = 0; mt < 4; mt++)
                ldsm_x4(af[mt], Ab + (co_w + mt * 16 + a_row) * ROWB + kc * 32 + a_kh);
            uint32_t bf[2][4];
#pragma unroll
            for (int p = 0; p < 2; p++)
                ldsm_x4(bf[p], Bb + p * 16 * ROWB + kc * 32);
#pragma unroll
            for (int mt = 0; mt < 4; mt++)
#pragma unroll
                for (int nt = 0; nt < 4; nt++)
                    mma_f16(acc[mt][nt], af[mt], bf[nt >> 1][(nt & 1) * 2], bf[nt >> 1][(nt & 1) * 2 + 1]);
        }
        __syncthreads();   // protect A buffers
    }

    // ---- epilogue: frags -> smem [128 t][132 co] -> coalesced stores + stats ----
    float* Ts = (float*)smem;
#pragma unroll
    for (int mt = 0; mt < 4; mt++)
#pragma unroll
        for (int nt = 0; nt < 4; nt++) {
            int co = co_w + mt * 16 + g;
            int t  = t_w + nt * 8 + tq * 2;
            Ts[t * 132 + co]           = acc[mt][nt][0];
            Ts[(t + 1) * 132 + co]     = acc[mt][nt][1];
            Ts[t * 132 + co + 8]       = acc[mt][nt][2];
            Ts[(t + 1) * 132 + co + 8] = acc[mt][nt][3];
        }
    __syncthreads();

    {
        int c = tid & 127;
        float s = 0.f, q = 0.f;
        for (int t = (tid >> 7); t < 125; t += 2) {
            float v = Ts[t * 132 + c];
            s += v; q += v * v;
            out[((b * TLEN + t0 + t) << 7) + c] = v;
        }
        atomicAdd(&osum[c], s);
        atomicAdd(&ossq[c], q);
    }
}

// ---------- launch ----------
extern "C" void kernel_launch(void* const* d_in, const int* in_sizes, int n_in,
                              void* d_out, int out_size) {
    const float* x  = (const float*)d_in[0];
    const float* w0 = (const float*)d_in[1];
    const float* w1 = (const float*)d_in[2];
    const float* w2 = (const float*)d_in[3];
    const float* w3 = (const float*)d_in[4];
    const float* ow = (const float*)d_in[5];
    const float* ob = (const float*)d_in[6];
    float* out = (float*)d_out;

    cudaFuncSetAttribute(conv_mma_kernel<9>, cudaFuncAttributeMaxDynamicSharedMemorySize, SMEM_SZ);
    cudaFuncSetAttribute(conv_mma_kernel<3>, cudaFuncAttributeMaxDynamicSharedMemorySize, SMEM_SZ);
    cudaFuncSetAttribute(conv_mma_kernel<1>, cudaFuncAttributeMaxDynamicSharedMemorySize, SMEM_SZ);

    float *pX,*pZ,*pK,*pY1,*pY2,*pY3,*pZA;
    __half *pW0,*pW1,*pW2,*pW3;
    float *ps1,*pq1,*pm1,*pr1,*ps2,*pq2,*pm2,*pr2,*ps3,*pq3,*pm3,*pr3;
    cudaGetSymbolAddress((void**)&pX,  g_X);
    cudaGetSymbolAddress((void**)&pZ,  g_Z);
    cudaGetSymbolAddress((void**)&pK,  g_K);
    cudaGetSymbolAddress((void**)&pY1, g_Y1);
    cudaGetSymbolAddress((void**)&pY2, g_Y2);
    cudaGetSymbolAddress((void**)&pY3, g_Y3);
    cudaGetSymbolAddress((void**)&pZA, g_ZA);
    cudaGetSymbolAddress((void**)&pW0, g_W0p);
    cudaGetSymbolAddress((void**)&pW1, g_W1p);
    cudaGetSymbolAddress((void**)&pW2, g_W2p);
    cudaGetSymbolAddress((void**)&pW3, g_W3p);
    cudaGetSymbolAddress((void**)&ps1, g_sum1); cudaGetSymbolAddress((void**)&pq1, g_ssq1);
    cudaGetSymbolAddress((void**)&pm1, g_m1);   cudaGetSymbolAddress((void**)&pr1, g_r1);
    cudaGetSymbolAddress((void**)&ps2, g_sum2); cudaGetSymbolAddress((void**)&pq2, g_ssq2);
    cudaGetSymbolAddress((void**)&pm2, g_m2);   cudaGetSymbolAddress((void**)&pr2, g_r2);
    cudaGetSymbolAddress((void**)&ps3, g_sum3); cudaGetSymbolAddress((void**)&pq3, g_ssq3);
    cudaGetSymbolAddress((void**)&pm3, g_m3);   cudaGetSymbolAddress((void**)&pr3, g_r3);

    const float dt = 0.25f;
    dim3 cgrid(4, 128);
    const int EW = (FSZ + 255) / 256;

    init_stats_kernel<<<1, 128>>>();
    prep_w_kernel<<<(3*128*136 + 255)/256, 256>>>(w0, pW0, 80, 3);
    prep_w_kernel<<<(9*128*136 + 255)/256, 256>>>(w1, pW1, 128, 9);
    prep_w_kernel<<<(9*128*136 + 255)/256, 256>>>(w2, pW2, 128, 9);
    prep_w_kernel<<<(1*128*136 + 255)/256, 256>>>(w3, pW3, 128, 1);
    xpose_kernel<<<EW, 256>>>(x, pX);

    // conv0 + BN + relu -> Z
    conv_mma_kernel<3><<<cgrid, 256, SMEM_SZ>>>(pX, nullptr, 0.f, pW0,
                                                nullptr, nullptr, pY1, ps1, pq1);
    finalize_stats_kernel<<<1, 128>>>(ps1, pq1, pm1, pr1, nullptr, nullptr, nullptr, nullptr);
    bn_relu_kernel<<<EW, 256>>>(pY1, pm1, pr1, pZ);

    for (int step = 0; step < 4; ++step) {
        for (int e = 0; e < 4; ++e) {
            float alpha = (e == 0) ? 0.f : (e == 3 ? dt : 0.5f * dt);
            const float* in2 = (e == 0) ? nullptr : (const float*)pK;

            conv_mma_kernel<9><<<cgrid, 256, SMEM_SZ>>>(pZ, in2, alpha, pW1,
                                                        nullptr, nullptr, pY1, ps1, pq1);
            conv_mma_kernel<1><<<cgrid, 256, SMEM_SZ>>>(pZ, in2, alpha, pW3,
                                                        nullptr, nullptr, pY3, ps3, pq3);
            finalize_stats_kernel<<<1, 128>>>(ps1, pq1, pm1, pr1, ps3, pq3, pm3, pr3);

            conv_mma_kernel<9><<<cgrid, 256, SMEM_SZ>>>(pY1, nullptr, 0.f, pW2,
                                                        pm1, pr1, pY2, ps2, pq2);
            finalize_stats_kernel<<<1, 128>>>(ps2, pq2, pm2, pr2, nullptr, nullptr, nullptr, nullptr);

            float wgt = (dt / 6.0f) * ((e == 0 || e == 3) ? 1.0f : 2.0f);
            int mode = (e == 0) ? 0 : (e == 3 ? 2 : 1);
            combine_kernel<<<EW, 256>>>(pY2, pY3, pm2, pr2, pm3, pr3,
                                        pZ, pK, pZA, pZ, wgt, mode);
        }
    }

    pool_head_kernel<<<128, 128>>>(pZ, ow, ob, out);
}

// round 8
// speedup vs baseline: 11.5271x; 1.2612x over previous
#include <cuda_runtime.h>
#include <cuda_fp16.h>
#include <cstdint>
#include <math.h>

#define BBATCH 128
#define TLEN   500
#define NLAB   35
#define FSZ    (128*500*128)     // [b][t][c] feature tensor
#define NELEM  64000.0f
#define BN_EPS 1e-5f

// ---------- device scratch ----------
__device__ float g_X[FSZ];
__device__ float g_Z[FSZ];
__device__ float g_K[FSZ];
__device__ float g_Y1[FSZ];
__device__ float g_Y2[FSZ];
__device__ float g_Y3[FSZ];
__device__ float g_ZA[FSZ];

// fp16 weight images: [tap][128 co][136 ci]
__device__ __half g_W0p[3*128*136];
__device__ __half g_W1p[9*128*136];
__device__ __half g_W2p[9*128*136];
__device__ __half g_W3p[1*128*136];

// per-conv-instance BN stat slots: [slot][0:128)=sum, [128:256)=ssq
#define NSLOTS 50
__device__ float g_stats[NSLOTS*256];

// ---------- helpers ----------
__device__ __forceinline__ uint32_t smem_u32(const void* p) {
    uint32_t a;
    asm("{ .reg .u64 t; cvta.to.shared.u64 t, %1; cvt.u32.u64 %0, t; }" : "=r"(a) : "l"(p));
    return a;
}
__device__ __forceinline__ void cp_async16(uint32_t dst, const void* src) {
    asm volatile("cp.async.cg.shared.global [%0], [%1], 16;" :: "r"(dst), "l"(src));
}
#define CP_COMMIT() asm volatile("cp.async.commit_group;" ::: "memory")
#define CP_WAIT(n)  asm volatile("cp.async.wait_group %0;" :: "n"(n) : "memory")

__device__ __forceinline__ void ldsm_x4(uint32_t* r, uint32_t addr) {
    asm volatile("ldmatrix.sync.aligned.m8n8.x4.shared.b16 {%0,%1,%2,%3}, [%4];"
        : "=r"(r[0]), "=r"(r[1]), "=r"(r[2]), "=r"(r[3]) : "r"(addr));
}
__device__ __forceinline__ void mma_f16(float* d, const uint32_t* a, uint32_t b0, uint32_t b1) {
    asm volatile("mma.sync.aligned.m16n8k16.row.col.f32.f16.f16.f32 "
        "{%0,%1,%2,%3}, {%4,%5,%6,%7}, {%8,%9}, {%0,%1,%2,%3};"
        : "+f"(d[0]), "+f"(d[1]), "+f"(d[2]), "+f"(d[3])
        : "r"(a[0]), "r"(a[1]), "r"(a[2]), "r"(a[3]), "r"(b0), "r"(b1));
}

// ---------- small kernels ----------
__global__ void init_stats_kernel() {
    g_stats[blockIdx.x * 256 + threadIdx.x] = 0.f;
}

// src [128 co][CIR][NK] -> img [tap][co][136] fp16
__global__ void prep_w_kernel(const float* __restrict__ src, __half* __restrict__ img,
                              int CIR, int NK) {
    int idx = blockIdx.x * 256 + threadIdx.x;
    int tot = NK * 128 * 136;
    if (idx >= tot) return;
    int tap = idx / (128 * 136);
    int rem = idx - tap * 128 * 136;
    int co = rem / 136, ci = rem - co * 136;
    float v = (ci < CIR) ? src[(co * CIR + ci) * NK + tap] : 0.f;
    img[idx] = __float2half_rn(v);
}

// x[b][80][500] -> X[b][t][c]
__global__ void xpose_kernel(const float* __restrict__ x, float* __restrict__ X) {
    int i = blockIdx.x * 256 + threadIdx.x;
    if (i >= FSZ) return;
    int c = i & 127, bt = i >> 7;
    int t = bt % TLEN, b = bt / TLEN;
    X[i] = (c < 80) ? x[(b * 80 + c) * TLEN + t] : 0.f;
}

__global__ void bn_relu_kernel(const float* __restrict__ Y, const float* __restrict__ bns,
                               float* __restrict__ Z) {
    __shared__ float ms[128], rs[128];
    int tid = threadIdx.x;
    if (tid < 128) {
        float m = bns[tid] * (1.f / NELEM);
        float v = bns[128 + tid] * (1.f / NELEM) - m * m;
        ms[tid] = m; rs[tid] = rsqrtf(v + BN_EPS);
    }
    __syncthreads();
    int i4 = blockIdx.x * 256 + tid;
    if (i4 * 4 >= FSZ) return;
    int c0 = (i4 * 4) & 127;
    float4 y = ((const float4*)Y)[i4];
    float4 o;
    o.x = fmaxf((y.x - ms[c0]) * rs[c0], 0.f);
    o.y = fmaxf((y.y - ms[c0+1]) * rs[c0+1], 0.f);
    o.z = fmaxf((y.z - ms[c0+2]) * rs[c0+2], 0.f);
    o.w = fmaxf((y.w - ms[c0+3]) * rs[c0+3], 0.f);
    ((float4*)Z)[i4] = o;
}

__global__ void combine_kernel(const float* __restrict__ Y2, const float* __restrict__ Y3,
                               const float* __restrict__ bns2, const float* __restrict__ bns3,
                               const float* __restrict__ Z, float* __restrict__ K,
                               float* __restrict__ ZA, float* __restrict__ Zout,
                               float wgt, int mode) {
    __shared__ float m2s[128], r2s[128], m3s[128], r3s[128];
    int tid = threadIdx.x;
    if (tid < 128) {
        float m = bns2[tid] * (1.f / NELEM);
        float v = bns2[128 + tid] * (1.f / NELEM) - m * m;
        m2s[tid] = m; r2s[tid] = rsqrtf(v + BN_EPS);
        m = bns3[tid] * (1.f / NELEM);
        v = bns3[128 + tid] * (1.f / NELEM) - m * m;
        m3s[tid] = m; r3s[tid] = rsqrtf(v + BN_EPS);
    }
    __syncthreads();
    int i4 = blockIdx.x * 256 + tid;
    if (i4 * 4 >= FSZ) return;
    int c0 = (i4 * 4) & 127;
    float4 y2 = ((const float4*)Y2)[i4];
    float4 y3 = ((const float4*)Y3)[i4];
    float4 kk;
    {
        float a = fmaxf((y3.x - m3s[c0]) * r3s[c0], 0.f);
        kk.x = fmaxf((y2.x - m2s[c0]) * r2s[c0] + a, 0.f);
        a = fmaxf((y3.y - m3s[c0+1]) * r3s[c0+1], 0.f);
        kk.y = fmaxf((y2.y - m2s[c0+1]) * r2s[c0+1] + a, 0.f);
        a = fmaxf((y3.z - m3s[c0+2]) * r3s[c0+2], 0.f);
        kk.z = fmaxf((y2.z - m2s[c0+2]) * r2s[c0+2] + a, 0.f);
        a = fmaxf((y3.w - m3s[c0+3]) * r3s[c0+3], 0.f);
        kk.w = fmaxf((y2.w - m2s[c0+3]) * r2s[c0+3] + a, 0.f);
    }
    ((float4*)K)[i4] = kk;
    float4 base;
    if (mode == 0) base = ((const float4*)Z)[i4];
    else           base = ((const float4*)ZA)[i4];
    float4 o;
    o.x = base.x + wgt * kk.x; o.y = base.y + wgt * kk.y;
    o.z = base.z + wgt * kk.z; o.w = base.w + wgt * kk.w;
    if (mode == 2) ((float4*)Zout)[i4] = o;
    else           ((float4*)ZA)[i4] = o;
}

__global__ void pool_head_kernel(const float* __restrict__ Z, const float* __restrict__ ow,
                                 const float* __restrict__ ob, float* __restrict__ out) {
    __shared__ float feat[128];
    int b = blockIdx.x, c = threadIdx.x;
    float s = 0.f;
    for (int t = 0; t < TLEN; t++) s += Z[((b * TLEN + t) << 7) + c];
    feat[c] = s * (1.0f / (float)TLEN);
    __syncthreads();
    if (c < NLAB) {
        float o = ob[c];
        for (int k = 0; k < 128; k++) o = fmaf(feat[k], ow[c * 128 + k], o);
        out[b * NLAB + c] = o;
    }
}

// ---------- mma.sync fp16 conv kernel ----------
#define NB      136
#define ROWB    272
#define B_OFF   0
#define A_OFF   (NB*ROWB)            // 36992
#define A_TAPB  34816                // 128 rows x 272
#define SM_STAT (A_OFF + 2*A_TAPB)   // 106624
#define SMEM_SZ (SM_STAT + 1024)     // 107648
#define A_CHUNKS (A_TAPB/16)         // 2176

// epilogue: frags -> Ts (A-buf0, two 64-row passes) -> coalesced stores + stat atomics
__device__ __forceinline__ void epilogue_store(
    char* smem, float acc[4][4][4], int co_w, int t_w, int g, int tq,
    int tid, int b, int t0, float* __restrict__ out, float* __restrict__ stat) {
    float* Ts = (float*)(smem + A_OFF);
    float s = 0.f, q = 0.f;
    const int c = tid & 127;
#pragma unroll
    for (int p = 0; p < 2; p++) {
        __syncthreads();
        if ((t_w >> 6) == p) {
#pragma unroll
            for (int mt = 0; mt < 4; mt++)
#pragma unroll
                for (int nt = 0; nt < 4; nt++) {
                    int co = co_w + mt * 16 + g;
                    int t  = (t_w & 63) + nt * 8 + tq * 2;
                    Ts[t * 132 + co]           = acc[mt][nt][0];
                    Ts[(t + 1) * 132 + co]     = acc[mt][nt][1];
                    Ts[t * 132 + co + 8]       = acc[mt][nt][2];
                    Ts[(t + 1) * 132 + co + 8] = acc[mt][nt][3];
                }
        }
        __syncthreads();
        for (int tl = (tid >> 7); tl < 64; tl += 2) {
            int tt = p * 64 + tl;
            if (tt < 125) {
                float v = Ts[tl * 132 + c];
                s += v; q += v * v;
                out[((b * TLEN + t0 + tt) << 7) + c] = v;
            }
        }
    }
    atomicAdd(&stat[c], s);
    atomicAdd(&stat[128 + c], q);
}

// CTA: batch b, 128 co x 125 t. B smem: 136 rows x 128 ci fp16 (row 272B).
// A (weights) cp.async double-buffered per tap. FUSE3: second 1x1 conv phase
// sharing staged B (W3 prefetched into A-buf1 during phase-1 epilogue).
template <int NTAPS, bool FUSE3>
__global__ __launch_bounds__(256, 2)
void conv_mma_kernel(const float* __restrict__ in, const float* __restrict__ in2, float alpha,
                     const __half* __restrict__ wimg, const __half* __restrict__ w3img,
                     const float* __restrict__ bns,
                     float* __restrict__ out, float* __restrict__ stat,
                     float* __restrict__ out3, float* __restrict__ stat3) {
    constexpr int R = NTAPS / 2;
    extern __shared__ char smem[];
    const uint32_t sb = smem_u32(smem);
    const int tid = threadIdx.x;
    const int t0 = blockIdx.x * 125;
    const int b  = blockIdx.y;

    const bool h2 = (in2 != nullptr), hbn = (bns != nullptr);

    // inline BN stats from raw sums
    float* sm_m = (float*)(smem + SM_STAT);
    float* sm_r = sm_m + 128;
    if (hbn) {
        if (tid < 128) {
            float m = bns[tid] * (1.f / NELEM);
            float v = bns[128 + tid] * (1.f / NELEM) - m * m;
            sm_m[tid] = m; sm_r[tid] = rsqrtf(v + BN_EPS);
        }
        __syncthreads();
    }

    // ---- stage B ----
    for (int idx = tid; idx < NB * 64; idx += 256) {
        int j = idx >> 6, pr = idx & 63;
        int u = t0 - R + j;
        float v0 = 0.f, v1 = 0.f;
        if (u >= 0 && u < TLEN) {
            const float* p = in + ((b * TLEN + u) << 7) + pr * 2;
            v0 = p[0]; v1 = p[1];
            if (h2) {
                const float* qq = in2 + ((b * TLEN + u) << 7) + pr * 2;
                v0 += alpha * qq[0]; v1 += alpha * qq[1];
            }
            if (hbn) {
                int c = pr * 2;
                v0 = fmaxf((v0 - sm_m[c]) * sm_r[c], 0.f);
                v1 = fmaxf((v1 - sm_m[c + 1]) * sm_r[c + 1], 0.f);
            }
        }
        *(__half2*)(smem + B_OFF + j * ROWB + pr * 4) = __floats2half2_rn(v0, v1);
    }

    // ---- prefetch A tap 0 ----
    for (int i = tid; i < A_CHUNKS; i += 256)
        cp_async16(sb + A_OFF + i * 16, (const char*)wimg + i * 16);
    CP_COMMIT();
    __syncthreads();

    const int wid = tid >> 5, lane = tid & 31;
    const int co_w = (wid & 1) * 64;
    const int t_w  = (wid >> 1) * 32;
    const int g  = lane >> 2;
    const int tq = lane & 3;
    const int a_row = lane & 15;
    const int a_kh  = (lane >> 4) * 16;
    const int quad = lane >> 3;
    const int b_nl = (lane & 7) + ((quad >> 1) * 8);
    const int b_kh = (quad & 1) * 16;

    float acc[4][4][4];
#pragma unroll
    for (int mt = 0; mt < 4; mt++)
#pragma unroll
        for (int nt = 0; nt < 4; nt++)
#pragma unroll
            for (int e = 0; e < 4; e++) acc[mt][nt][e] = 0.f;

#pragma unroll 1
    for (int tap = 0; tap < NTAPS; tap++) {
        const int buf = tap & 1;
        if (tap + 1 < NTAPS) {
            const char* src = (const char*)wimg + (size_t)(tap + 1) * A_TAPB;
            uint32_t dst = sb + A_OFF + ((tap + 1) & 1) * A_TAPB;
            for (int i = tid; i < A_CHUNKS; i += 256) cp_async16(dst + i * 16, src + i * 16);
            CP_COMMIT();
            CP_WAIT(1);
        } else {
            CP_WAIT(0);
        }
        __syncthreads();

        const uint32_t Ab = sb + A_OFF + buf * A_TAPB;
        const uint32_t Bb = sb + B_OFF + (t_w + tap + b_nl) * ROWB + b_kh;

#pragma unroll
        for (int kc = 0; kc < 8; kc++) {
            uint32_t af[4][4];
#pragma unroll
            for (int mt = 0; mt < 4; mt++)
                ldsm_x4(af[mt], Ab + (co_w + mt * 16 + a_row) * ROWB + kc * 32 + a_kh);
            uint32_t bf[2][4];
#pragma unroll
            for (int p = 0; p < 2; p++)
                ldsm_x4(bf[p], Bb + p * 16 * ROWB + kc * 32);
#pragma unroll
            for (int mt = 0; mt < 4; mt++)
#pragma unroll
                for (int nt = 0; nt < 4; nt++)
                    mma_f16(acc[mt][nt], af[mt], bf[nt >> 1][(nt & 1) * 2], bf[nt >> 1][(nt & 1) * 2 + 1]);
        }
        __syncthreads();
    }

    if (FUSE3) {
        // prefetch W3 into A-buf1 (tap NTAPS-1 used buf0; buf1 free)
        for (int i = tid; i < A_CHUNKS; i += 256)
            cp_async16(sb + A_OFF + A_TAPB + i * 16, (const char*)w3img + i * 16);
        CP_COMMIT();
    }

    epilogue_store(smem, acc, co_w, t_w, g, tq, tid, b, t0, out, stat);

    if (FUSE3) {
        CP_WAIT(0);
        __syncthreads();
#pragma unroll
        for (int mt = 0; mt < 4; mt++)
#pragma unroll
            for (int nt = 0; nt < 4; nt++)
#pragma unroll
                for (int e = 0; e < 4; e++) acc[mt][nt][e] = 0.f;

        const uint32_t Ab = sb + A_OFF + A_TAPB;
        const uint32_t Bb = sb + B_OFF + (t_w + R + b_nl) * ROWB + b_kh;
#pragma unroll
        for (int kc = 0; kc < 8; kc++) {
            uint32_t af[4][4];
#pragma unroll
            for (int mt = 0; mt < 4; mt++)
                ldsm_x4(af[mt], Ab + (co_w + mt * 16 + a_row) * ROWB + kc * 32 + a_kh);
            uint32_t bf[2][4];
#pragma unroll
            for (int p = 0; p < 2; p++)
                ldsm_x4(bf[p], Bb + p * 16 * ROWB + kc * 32);
#pragma unroll
            for (int mt = 0; mt < 4; mt++)
#pragma unroll
                for (int nt = 0; nt < 4; nt++)
                    mma_f16(acc[mt][nt], af[mt], bf[nt >> 1][(nt & 1) * 2], bf[nt >> 1][(nt & 1) * 2 + 1]);
        }
        epilogue_store(smem, acc, co_w, t_w, g, tq, tid, b, t0, out3, stat3);
    }
}

// ---------- launch ----------
extern "C" void kernel_launch(void* const* d_in, const int* in_sizes, int n_in,
                              void* d_out, int out_size) {
    const float* x  = (const float*)d_in[0];
    const float* w0 = (const float*)d_in[1];
    const float* w1 = (const float*)d_in[2];
    const float* w2 = (const float*)d_in[3];
    const float* w3 = (const float*)d_in[4];
    const float* ow = (const float*)d_in[5];
    const float* ob = (const float*)d_in[6];
    float* out = (float*)d_out;

    cudaFuncSetAttribute(conv_mma_kernel<9, true>,  cudaFuncAttributeMaxDynamicSharedMemorySize, SMEM_SZ);
    cudaFuncSetAttribute(conv_mma_kernel<9, false>, cudaFuncAttributeMaxDynamicSharedMemorySize, SMEM_SZ);
    cudaFuncSetAttribute(conv_mma_kernel<3, false>, cudaFuncAttributeMaxDynamicSharedMemorySize, SMEM_SZ);

    float *pX,*pZ,*pK,*pY1,*pY2,*pY3,*pZA,*pS;
    __half *pW0,*pW1,*pW2,*pW3;
    cudaGetSymbolAddress((void**)&pX,  g_X);
    cudaGetSymbolAddress((void**)&pZ,  g_Z);
    cudaGetSymbolAddress((void**)&pK,  g_K);
    cudaGetSymbolAddress((void**)&pY1, g_Y1);
    cudaGetSymbolAddress((void**)&pY2, g_Y2);
    cudaGetSymbolAddress((void**)&pY3, g_Y3);
    cudaGetSymbolAddress((void**)&pZA, g_ZA);
    cudaGetSymbolAddress((void**)&pW0, g_W0p);
    cudaGetSymbolAddress((void**)&pW1, g_W1p);
    cudaGetSymbolAddress((void**)&pW2, g_W2p);
    cudaGetSymbolAddress((void**)&pW3, g_W3p);
    cudaGetSymbolAddress((void**)&pS,  g_stats);

    const float dt = 0.25f;
    dim3 cgrid(4, 128);
    const int EW = (FSZ + 255) / 256;
    const int EW4 = (FSZ / 4 + 255) / 256;

    init_stats_kernel<<<NSLOTS, 256>>>();
    prep_w_kernel<<<(3*128*136 + 255)/256, 256>>>(w0, pW0, 80, 3);
    prep_w_kernel<<<(9*128*136 + 255)/256, 256>>>(w1, pW1, 128, 9);
    prep_w_kernel<<<(9*128*136 + 255)/256, 256>>>(w2, pW2, 128, 9);
    prep_w_kernel<<<(1*128*136 + 255)/256, 256>>>(w3, pW3, 128, 1);
    xpose_kernel<<<EW, 256>>>(x, pX);

    // conv0 -> Y1 (+slot 0), then BN+relu -> Z
    conv_mma_kernel<3, false><<<cgrid, 256, SMEM_SZ>>>(pX, nullptr, 0.f, pW0, nullptr,
                                                       nullptr, pY1, pS, nullptr, nullptr);
    bn_relu_kernel<<<EW4, 256>>>(pY1, pS, pZ);

    for (int step = 0; step < 4; ++step) {
        for (int e = 0; e < 4; ++e) {
            float alpha = (e == 0) ? 0.f : (e == 3 ? dt : 0.5f * dt);
            const float* in2 = (e == 0) ? nullptr : (const float*)pK;
            int si = 1 + (step * 4 + e) * 3;
            float* slotA = pS + si * 256;        // conv1 stats
            float* slotB = pS + (si + 1) * 256;  // conv3 stats
            float* slotC = pS + (si + 2) * 256;  // conv2 stats

            // fused conv1(9-tap) + conv3(1x1), shared staged B
            conv_mma_kernel<9, true><<<cgrid, 256, SMEM_SZ>>>(pZ, in2, alpha, pW1, pW3,
                                                              nullptr, pY1, slotA, pY3, slotB);
            // conv2 with inline BN+relu of Y1 from slotA
            conv_mma_kernel<9, false><<<cgrid, 256, SMEM_SZ>>>(pY1, nullptr, 0.f, pW2, nullptr,
                                                               slotA, pY2, slotC, nullptr, nullptr);
            float wgt = (dt / 6.0f) * ((e == 0 || e == 3) ? 1.0f : 2.0f);
            int mode = (e == 0) ? 0 : (e == 3 ? 2 : 1);
            combine_kernel<<<EW4, 256>>>(pY2, pY3, slotC, slotB, pZ, pK, pZA, pZ, wgt, mode);
        }
    }

    pool_head_kernel<<<128, 128>>>(pZ, ow, ob, out);
}